// round 15
// baseline (speedup 1.0000x reference)
#include <cuda_runtime.h>

#define NN 100000
#define EE 1600000
#define BLKF 256

// ---- device scratch (zero-init at load; invariants restored each call) ----
__device__ int    g_src32[EE];
__device__ int    g_dst32[EE];
__device__ float  g_deg[NN];        // reset to 0 in node1 phase
__device__ float  g_dinv[NN];
__device__ float  g_px[NN];
__device__ float  g_s[NN];
__device__ float2 g_pq[NN];
__device__ float2 g_PQ[NN];
__device__ float  g_agg[NN * 16];   // fallback; reset in k_out
__device__ unsigned g_bar_cnt;      // returns to 0 after every barrier
__device__ unsigned g_bar_phase;    // monotonic across graph replays

__device__ __forceinline__ void red2(float2* a, float2 v) {
    asm volatile("red.add.v2.f32 [%0], {%1, %2};"
                 :: "l"(a), "f"(v.x), "f"(v.y) : "memory");
}

// grid barrier: all nblocks co-resident (grid sized via occupancy API)
__device__ __forceinline__ void gbar(unsigned target, int nblocks) {
    __syncthreads();
    if (threadIdx.x == 0) {
        __threadfence();
        unsigned old = atomicAdd(&g_bar_cnt, 1u);
        if (old == (unsigned)nblocks - 1u) {
            g_bar_cnt = 0u;                 // safe: nobody touches cnt until released
            __threadfence();
            atomicAdd(&g_bar_phase, 1u);    // release
        } else {
            unsigned p;
            do {
                asm volatile("ld.acquire.gpu.u32 %0, [%1];" : "=r"(p) : "l"(&g_bar_phase));
                if (p >= target) break;
                __nanosleep(64);
            } while (true);
        }
        __threadfence();
    }
    __syncthreads();
}

// ==== Kernel A: persistent edge pipeline (low-reg phases only) ====
__global__ void __launch_bounds__(BLKF, 8) k_pipe(
        const void* __restrict__ eiv, const float* __restrict__ x,
        const float* __restrict__ W1, const float* __restrict__ b1,
        int E, int N, int nblocks) {
    __shared__ unsigned s_base;
    __shared__ int s_is64, s_bz, s_bad;
    __shared__ float sW1[16], sb1[16];

    const int t = threadIdx.x;
    if (t == 0) { s_base = g_bar_phase; s_bad = 0; }
    __syncthreads();
    if (t < 256 && t < E) {
        long long v = ((const long long*)eiv)[t];  // in-bounds under both layouts
        if (v < 0 || v >= (long long)N) atomicExch(&s_bad, 1);
    }
    if (t < 16) { sW1[t] = W1[t]; sb1[t] = b1[t]; }
    __syncthreads();
    if (t == 0) {
        s_is64 = !s_bad;
        int z = 1;
        for (int k = 0; k < 16; k++)
            if (sb1[k] != 0.f) z = 0;
        s_bz = z;
    }
    __syncthreads();
    const int is64 = s_is64, bz = s_bz;
    const unsigned base = s_base;
    const int T   = nblocks * BLKF;
    const int gid = blockIdx.x * BLKF + t;
    const int Q   = E >> 2;

    // ---- P1: degree REDs (+ int64->int32 conversion) ----
    if (is64) {
        const long long* ei = (const long long*)eiv;
        for (int q = gid; q < Q; q += T) {
            int e4 = 4 * q;
            longlong2 sA = *reinterpret_cast<const longlong2*>(ei + e4);
            longlong2 sB = *reinterpret_cast<const longlong2*>(ei + e4 + 2);
            longlong2 dA = *reinterpret_cast<const longlong2*>(ei + E + e4);
            longlong2 dB = *reinterpret_cast<const longlong2*>(ei + E + e4 + 2);
            int4 sv = make_int4((int)sA.x, (int)sA.y, (int)sB.x, (int)sB.y);
            int4 dv = make_int4((int)dA.x, (int)dA.y, (int)dB.x, (int)dB.y);
            *reinterpret_cast<int4*>(&g_src32[e4]) = sv;
            *reinterpret_cast<int4*>(&g_dst32[e4]) = dv;
            atomicAdd(&g_deg[dv.x], 1.f); atomicAdd(&g_deg[dv.y], 1.f);
            atomicAdd(&g_deg[dv.z], 1.f); atomicAdd(&g_deg[dv.w], 1.f);
        }
        for (int e = 4 * Q + gid; e < E; e += T) {
            int s = (int)ei[e], d = (int)ei[E + e];
            g_src32[e] = s; g_dst32[e] = d;
            atomicAdd(&g_deg[d], 1.f);
        }
    } else {
        const int* dst = (const int*)eiv + E;
        for (int q = gid; q < Q; q += T) {
            int4 dv = *reinterpret_cast<const int4*>(dst + 4 * q);
            atomicAdd(&g_deg[dv.x], 1.f); atomicAdd(&g_deg[dv.y], 1.f);
            atomicAdd(&g_deg[dv.z], 1.f); atomicAdd(&g_deg[dv.w], 1.f);
        }
        for (int e = 4 * Q + gid; e < E; e += T)
            atomicAdd(&g_deg[dst[e]], 1.f);
    }
    gbar(base + 1, nblocks);

    // ---- P2: dinv; px; raw s init; reset deg invariant ----
    for (int v = gid; v < N; v += T) {
        float dg = g_deg[v];
        g_deg[v] = 0.f;
        float dv = rsqrtf(dg + 1.0f);
        g_dinv[v] = dv;
        float pxv = dv * x[v];
        g_px[v] = pxv;
        g_s[v]  = pxv;
    }
    gbar(base + 2, nblocks);

    // ---- P3: layer-1 scatter (edges L2-hot from P1) ----
    const int* srcp = is64 ? g_src32 : (const int*)eiv;
    const int* dstp = is64 ? g_dst32 : (const int*)eiv + E;
    for (int q = gid; q < Q; q += T) {
        int e4 = 4 * q;
        int4 s = *reinterpret_cast<const int4*>(srcp + e4);
        int4 d = *reinterpret_cast<const int4*>(dstp + e4);
        float a0 = __ldg(&g_px[s.x]), a1 = __ldg(&g_px[s.y]);
        float a2 = __ldg(&g_px[s.z]), a3 = __ldg(&g_px[s.w]);
        atomicAdd(&g_s[d.x], a0); atomicAdd(&g_s[d.y], a1);
        atomicAdd(&g_s[d.z], a2); atomicAdd(&g_s[d.w], a3);
    }
    for (int e = 4 * Q + gid; e < E; e += T)
        atomicAdd(&g_s[dstp[e]], __ldg(&g_px[srcp[e]]));
    gbar(base + 3, nblocks);

    // ---- P4: finalize s; pq split; PQ init ----
    for (int v = gid; v < N; v += T) {
        float dv = g_dinv[v];
        float s  = dv * g_s[v];
        g_s[v]   = s;
        float2 pq = make_float2(dv * fmaxf(s, 0.f), dv * fminf(s, 0.f));
        g_pq[v] = pq;
        g_PQ[v] = pq;
    }
    gbar(base + 4, nblocks);

    // ---- P5: layer-2 scatter ----
    if (bz) {
        for (int q = gid; q < Q; q += T) {
            int e4 = 4 * q;
            int4 s = *reinterpret_cast<const int4*>(srcp + e4);
            int4 d = *reinterpret_cast<const int4*>(dstp + e4);
            float2 t0 = __ldg(&g_pq[s.x]), t1 = __ldg(&g_pq[s.y]);
            float2 t2 = __ldg(&g_pq[s.z]), t3 = __ldg(&g_pq[s.w]);
            red2(&g_PQ[d.x], t0); red2(&g_PQ[d.y], t1);
            red2(&g_PQ[d.z], t2); red2(&g_PQ[d.w], t3);
        }
        for (int e = 4 * Q + gid; e < E; e += T)
            red2(&g_PQ[dstp[e]], __ldg(&g_pq[srcp[e]]));
    } else {
        for (int e = gid; e < E; e += T) {
            int s = srcp[e], d = dstp[e];
            float sv = __ldg(&g_s[s]);
            float ns = __ldg(&g_dinv[s]);
#pragma unroll
            for (int k = 0; k < 16; k++) {
                float h = fmaxf(sv * sW1[k] + sb1[k], 0.f);
                atomicAdd(&g_agg[(size_t)d * 16 + k], ns * h);
            }
        }
    }
}

// ==== Kernel B: register-heavy output projection ====
__global__ void k_out(const float* __restrict__ W1, const float* __restrict__ b1,
                      const float* __restrict__ W2, const float* __restrict__ b2,
                      float* __restrict__ out, int n) {
    __shared__ float sc1[32], sc2[32], sb2s[32];
    __shared__ float sW2[512];
    __shared__ float sW1[16], sb1[16];
    __shared__ int s_bz;
    int t = threadIdx.x;
    if (t < 16) { sW1[t] = W1[t]; sb1[t] = b1[t]; }
    __syncthreads();
    if (t == 0) {
        int z = 1;
        for (int k = 0; k < 16; k++)
            if (sb1[k] != 0.f) z = 0;
        s_bz = z;
    }
    if (t < 32) {
        float c1 = 0.f, c2 = 0.f;
#pragma unroll
        for (int k = 0; k < 16; k++) {
            float w  = W1[k];
            float wv = W2[k * 32 + t];
            c1 += fmaxf(w, 0.f) * wv;
            c2 += fminf(w, 0.f) * wv;
        }
        sc1[t] = c1; sc2[t] = c2; sb2s[t] = b2[t];
    }
    for (int k = t; k < 512; k += blockDim.x) sW2[k] = W2[k];
    __syncthreads();
    int bz = s_bz;
    int v = blockIdx.x * blockDim.x + t;
    if (v >= n) return;

    float o[32];
    float dv = g_dinv[v];
    if (bz) {
        float2 PQ = g_PQ[v];
        float P = dv * PQ.x, Q = dv * PQ.y;
#pragma unroll
        for (int j = 0; j < 32; j++) o[j] = P * sc1[j] + Q * sc2[j] + sb2s[j];
    } else {
        float sv = g_s[v];
        float n2 = dv * dv;
        float tot[16];
        float4* a = reinterpret_cast<float4*>(&g_agg[(size_t)v * 16]);
        float4 zz = make_float4(0.f, 0.f, 0.f, 0.f);
#pragma unroll
        for (int q4 = 0; q4 < 4; q4++) {
            float4 av = a[q4];
            a[q4] = zz;            // reset invariant for next replay
            tot[4 * q4 + 0] = av.x; tot[4 * q4 + 1] = av.y;
            tot[4 * q4 + 2] = av.z; tot[4 * q4 + 3] = av.w;
        }
#pragma unroll
        for (int k = 0; k < 16; k++) {
            float h = fmaxf(sv * sW1[k] + sb1[k], 0.f);
            tot[k] = dv * tot[k] + n2 * h;
        }
#pragma unroll
        for (int j = 0; j < 32; j++) {
            float acc = sb2s[j];
#pragma unroll
            for (int k = 0; k < 16; k++) acc += tot[k] * sW2[k * 32 + j];
            o[j] = acc;
        }
    }
    float4* po = reinterpret_cast<float4*>(out + (size_t)v * 32);
#pragma unroll
    for (int j = 0; j < 8; j++)
        po[j] = make_float4(o[4 * j], o[4 * j + 1], o[4 * j + 2], o[4 * j + 3]);
}

extern "C" void kernel_launch(void* const* d_in, const int* in_sizes, int n_in,
                              void* d_out, int out_size) {
    const float* x  = (const float*)d_in[0];
    const void*  ei = d_in[1];
    const float* W1 = (const float*)d_in[2];
    const float* b1 = (const float*)d_in[3];
    const float* W2 = (const float*)d_in[4];
    const float* b2 = (const float*)d_in[5];
    float* out = (float*)d_out;

    int N = in_sizes[0];
    int E = in_sizes[1] / 2;

    int dev = 0, sms = 0, maxb = 0;
    cudaGetDevice(&dev);
    cudaDeviceGetAttribute(&sms, cudaDevAttrMultiProcessorCount, dev);
    cudaOccupancyMaxActiveBlocksPerMultiprocessor(&maxb, k_pipe, BLKF, 0);
    if (sms <= 0) sms = 148;
    if (maxb <= 0) maxb = 1;
    int grid = sms * maxb;   // one co-resident wave -> grid barrier safe

    k_pipe<<<grid, BLKF>>>(ei, x, W1, b1, E, N, grid);
    int gN = (N + BLKF - 1) / BLKF;
    k_out<<<gN, BLKF>>>(W1, b1, W2, b2, out, N);
}

// round 17
// speedup vs baseline: 1.1869x; 1.1869x over previous
#include <cuda_runtime.h>

#define NN 100000
#define EE 1600000
#define BLK 256

// ---- device scratch (no allocations allowed) ----
__device__ int    g_src32[EE];     // int64->int32 converted edges (only if needed)
__device__ int    g_dst32[EE];
__device__ float  g_deg[NN];
__device__ float  g_dinv[NN];
__device__ float  g_px[NN];        // dinv[v]*x[v]
__device__ float  g_s[NN];         // raw layer-1 aggregate, then finalized s
__device__ float2 g_pq[NN];        // dinv[v]*(max(s,0), min(s,0))
__device__ float2 g_PQ[NN];        // raw layer-2 (P,Q) aggregate (incl. self term)
__device__ float  g_agg[NN * 16];  // general-path fallback aggregate
__device__ float  g_c[64];         // c1=relu(W1)@W2, c2=min(W1,0)@W2
__device__ int    g_b1zero;
__device__ int    g_is64;

__device__ __forceinline__ int4 ldcs4(const int* p) {
    return __ldcs(reinterpret_cast<const int4*>(p));
}

__device__ __forceinline__ void red2(float2* addr, float2 v) {
    asm volatile("red.add.v2.f32 [%0], {%1, %2};"
                 :: "l"(addr), "f"(v.x), "f"(v.y) : "memory");
}

// ---- setup: dtype probe + fused coefficients + zero degree array ----
__global__ void k_setup(const void* __restrict__ ei, const float* __restrict__ W1,
                        const float* __restrict__ b1, const float* __restrict__ W2,
                        int E, int N) {
    int tid = threadIdx.x;
    if (blockIdx.x == 0) {
        __shared__ int bad;
        if (tid == 0) bad = 0;
        __syncthreads();
        if (tid < E) {
            long long v = ((const long long*)ei)[tid];  // first 256 slots: in-bounds both layouts
            if (v < 0 || v >= (long long)N) atomicExch(&bad, 1);
        }
        __syncthreads();
        if (tid == 0) {
            g_is64 = !bad;
            int z = 1;
            for (int k = 0; k < 16; k++)
                if (b1[k] != 0.f) z = 0;
            g_b1zero = z;
        }
        if (tid < 32) {
            float c1 = 0.f, c2 = 0.f;
#pragma unroll
            for (int k = 0; k < 16; k++) {
                float w  = W1[k];
                float wv = W2[k * 32 + tid];
                c1 += fmaxf(w, 0.f) * wv;
                c2 += fminf(w, 0.f) * wv;
            }
            g_c[tid] = c1;
            g_c[32 + tid] = c2;
        }
    }
    int v = blockIdx.x * BLK + tid;
    if (v < N) {
        g_deg[v] = 0.f;
        bool bz = true;
#pragma unroll
        for (int k = 0; k < 16; k++)
            if (b1[k] != 0.f) bz = false;
        if (!bz) {
            float4 z = make_float4(0.f, 0.f, 0.f, 0.f);
            float4* a = reinterpret_cast<float4*>(&g_agg[(size_t)v * 16]);
            a[0] = z; a[1] = z; a[2] = z; a[3] = z;
        }
    }
}

// ---- pass 1: degree atomics (+ one-time int64->int32 conversion), 4 edges/thread ----
__global__ void __launch_bounds__(BLK) k_deg(const void* __restrict__ eiv, int E) {
    int e0 = 4 * (blockIdx.x * blockDim.x + threadIdx.x);
    if (e0 >= E) return;
    if (g_is64) {
        const long long* ei = (const long long*)eiv;
        if (e0 + 3 < E) {
            longlong2 s01 = __ldcs(reinterpret_cast<const longlong2*>(ei + e0));
            longlong2 s23 = __ldcs(reinterpret_cast<const longlong2*>(ei + e0 + 2));
            longlong2 d01 = __ldcs(reinterpret_cast<const longlong2*>(ei + E + e0));
            longlong2 d23 = __ldcs(reinterpret_cast<const longlong2*>(ei + E + e0 + 2));
            int4 sv = make_int4((int)s01.x, (int)s01.y, (int)s23.x, (int)s23.y);
            int4 dv = make_int4((int)d01.x, (int)d01.y, (int)d23.x, (int)d23.y);
            *reinterpret_cast<int4*>(&g_src32[e0]) = sv;
            *reinterpret_cast<int4*>(&g_dst32[e0]) = dv;
            atomicAdd(&g_deg[dv.x], 1.f);
            atomicAdd(&g_deg[dv.y], 1.f);
            atomicAdd(&g_deg[dv.z], 1.f);
            atomicAdd(&g_deg[dv.w], 1.f);
        } else {
            for (int e = e0; e < E; e++) {
                int s = (int)ei[e], d = (int)ei[E + e];
                g_src32[e] = s; g_dst32[e] = d;
                atomicAdd(&g_deg[d], 1.f);
            }
        }
    } else {
        const int* dst = (const int*)eiv + E;
        if (e0 + 3 < E) {
            int4 dv = ldcs4(dst + e0);
            atomicAdd(&g_deg[dv.x], 1.f);
            atomicAdd(&g_deg[dv.y], 1.f);
            atomicAdd(&g_deg[dv.z], 1.f);
            atomicAdd(&g_deg[dv.w], 1.f);
        } else {
            for (int e = e0; e < E; e++) atomicAdd(&g_deg[dst[e]], 1.f);
        }
    }
}

// ---- pass 2: dinv = rsqrt(deg+1); px; raw s init = self term ----
__global__ void k_node1(const float* __restrict__ x, int n) {
    int v = blockIdx.x * blockDim.x + threadIdx.x;
    if (v >= n) return;
    float dv  = rsqrtf(g_deg[v] + 1.0f);
    g_dinv[v] = dv;
    float pxv = dv * x[v];
    g_px[v]   = pxv;
    g_s[v]    = pxv;
}

// ---- pass 3: layer-1 raw scatter: s_raw[dst] += px[src], 4 edges/thread ----
__global__ void __launch_bounds__(BLK) k_scat1(const void* __restrict__ eiv, int E) {
    const int* srcp = g_is64 ? g_src32 : (const int*)eiv;
    const int* dstp = g_is64 ? g_dst32 : (const int*)eiv + E;
    int e0 = 4 * (blockIdx.x * blockDim.x + threadIdx.x);
    if (e0 >= E) return;
    if (e0 + 3 < E) {
        int4 s = ldcs4(srcp + e0);
        int4 d = ldcs4(dstp + e0);
        float a0 = __ldg(&g_px[s.x]), a1 = __ldg(&g_px[s.y]);
        float a2 = __ldg(&g_px[s.z]), a3 = __ldg(&g_px[s.w]);
        atomicAdd(&g_s[d.x], a0); atomicAdd(&g_s[d.y], a1);
        atomicAdd(&g_s[d.z], a2); atomicAdd(&g_s[d.w], a3);
    } else {
        for (int e = e0; e < E; e++)
            atomicAdd(&g_s[dstp[e]], __ldg(&g_px[srcp[e]]));
    }
}

// ---- pass 4: finalize s; pq split; raw PQ init = self term ----
__global__ void k_node2(int n) {
    int v = blockIdx.x * blockDim.x + threadIdx.x;
    if (v >= n) return;
    float dv = g_dinv[v];
    float s  = dv * g_s[v];
    g_s[v]   = s;
    float p = fmaxf(s, 0.f), q = fminf(s, 0.f);
    float2 pq = make_float2(dv * p, dv * q);
    g_pq[v] = pq;
    g_PQ[v] = pq;
}

// ---- pass 5: layer-2 raw scatter, 4 edges/thread, 1 v2-RED/edge ----
__global__ void __launch_bounds__(BLK) k_scat2(const void* __restrict__ eiv,
                                               const float* __restrict__ W1,
                                               const float* __restrict__ b1, int E) {
    const int* srcp = g_is64 ? g_src32 : (const int*)eiv;
    const int* dstp = g_is64 ? g_dst32 : (const int*)eiv + E;
    int bz = g_b1zero;
    int e0 = 4 * (blockIdx.x * blockDim.x + threadIdx.x);
    if (e0 >= E) return;
    if (bz) {
        if (e0 + 3 < E) {
            int4 s = ldcs4(srcp + e0);
            int4 d = ldcs4(dstp + e0);
            float2 t0 = __ldg(&g_pq[s.x]), t1 = __ldg(&g_pq[s.y]);
            float2 t2 = __ldg(&g_pq[s.z]), t3 = __ldg(&g_pq[s.w]);
            red2(&g_PQ[d.x], t0); red2(&g_PQ[d.y], t1);
            red2(&g_PQ[d.z], t2); red2(&g_PQ[d.w], t3);
        } else {
            for (int e = e0; e < E; e++) red2(&g_PQ[dstp[e]], __ldg(&g_pq[srcp[e]]));
        }
    } else {
        __shared__ float sW1[16], sb1[16];
        if (threadIdx.x < 16) { sW1[threadIdx.x] = W1[threadIdx.x]; sb1[threadIdx.x] = b1[threadIdx.x]; }
        __syncthreads();
        int eEnd = min(e0 + 4, E);
        for (int e = e0; e < eEnd; e++) {
            int s = srcp[e], d = dstp[e];
            float sv = __ldg(&g_s[s]);
            float ns = __ldg(&g_dinv[s]);
#pragma unroll
            for (int k = 0; k < 16; k++) {
                float h = fmaxf(sv * sW1[k] + sb1[k], 0.f);
                atomicAdd(&g_agg[(size_t)d * 16 + k], ns * h);
            }
        }
    }
}

// ---- pass 6: output projection — warp per node, lane per output ----
// idx = v*32 + j; node loads are warp-uniform broadcasts; stores fully coalesced.
__global__ void __launch_bounds__(BLK) k_out(
        const float* __restrict__ W1, const float* __restrict__ b1,
        const float* __restrict__ W2, const float* __restrict__ b2,
        float* __restrict__ out, int n) {
    __shared__ float sc[64];
    __shared__ float sb2[32];
    __shared__ float sW2[512];
    __shared__ float sW1[16], sb1[16];
    int bz = g_b1zero;
    int t = threadIdx.x;
    if (t < 64) sc[t] = g_c[t];
    if (t < 32) sb2[t] = b2[t];
    if (!bz) {
        for (int k = t; k < 512; k += BLK) sW2[k] = W2[k];
        if (t < 16) { sW1[t] = W1[t]; sb1[t] = b1[t]; }
    }
    __syncthreads();

    int idx = blockIdx.x * BLK + t;      // element index = v*32 + j
    int v = idx >> 5;
    int j = idx & 31;
    if (v >= n) return;

    float dv = g_dinv[v];                 // warp-uniform -> broadcast
    float o;
    if (bz) {
        float2 PQ = g_PQ[v];              // warp-uniform -> broadcast (1 sector)
        float P = dv * PQ.x, Q = dv * PQ.y;
        o = fmaf(P, sc[j], fmaf(Q, sc[32 + j], sb2[j]));
    } else {
        float sv = g_s[v];
        float n2 = dv * dv;
        float acc = sb2[j];
        const float* a = &g_agg[(size_t)v * 16];
#pragma unroll
        for (int k = 0; k < 16; k++) {
            float h  = fmaxf(sv * sW1[k] + sb1[k], 0.f);
            float tk = dv * a[k] + n2 * h;   // a[k] warp-uniform
            acc = fmaf(tk, sW2[k * 32 + j], acc);
        }
        o = acc;
        // lanes 0..3 restore g_agg zero invariant for the next replay
        if (j < 4) {
            float4 z = make_float4(0.f, 0.f, 0.f, 0.f);
            reinterpret_cast<float4*>(&g_agg[(size_t)v * 16])[j] = z;
        }
    }
    out[(size_t)v * 32 + j] = o;          // fully coalesced per warp
}

extern "C" void kernel_launch(void* const* d_in, const int* in_sizes, int n_in,
                              void* d_out, int out_size) {
    const float* x  = (const float*)d_in[0];
    const void*  ei = d_in[1];
    const float* W1 = (const float*)d_in[2];
    const float* b1 = (const float*)d_in[3];
    const float* W2 = (const float*)d_in[4];
    const float* b2 = (const float*)d_in[5];
    float* out = (float*)d_out;

    int N = in_sizes[0];
    int E = in_sizes[1] / 2;

    int gN   = (N + BLK - 1) / BLK;
    int gE4  = ((E + 3) / 4 + BLK - 1) / BLK;
    int gOut = (N * 32 + BLK - 1) / BLK;

    k_setup<<<gN, BLK>>>(ei, W1, b1, W2, E, N);
    k_deg<<<gE4, BLK>>>(ei, E);
    k_node1<<<gN, BLK>>>(x, N);
    k_scat1<<<gE4, BLK>>>(ei, E);
    k_node2<<<gN, BLK>>>(N);
    k_scat2<<<gE4, BLK>>>(ei, W1, b1, E);
    k_out<<<gOut, BLK>>>(W1, b1, W2, b2, out, N);
}